// round 5
// baseline (speedup 1.0000x reference)
#include <cuda_runtime.h>
#include <cstdint>

#define N_IMG 16
#define CIN   32
#define COUT  32
#define HH    256
#define WW    256
#define HW    (HH * WW)
#define EPSV  1e-5f

// ---- scratch (no allocations allowed -> __device__ globals) ----
__device__ uint32_t g_xpack[N_IMG * HW];   // packed sign bits, bit c = (x[c] >= 0)

// ============================================================================
// Pack x: NCHW f32 -> per-pixel 32-bit sign word. Thread = 4 pixels.
// Channels staged in batches of 8 float4 -> MLP ~8. Block=128 for smoother
// SM residency (2048 blocks).
// ============================================================================
__global__ __launch_bounds__(128) void pack_x_kernel(const float* __restrict__ x) {
    int g  = blockIdx.x * 128 + threadIdx.x;
    int p0 = g << 2;
    int n  = p0 >> 16;                     // HW = 65536
    int s  = p0 & (HW - 1);
    const float4* xp = reinterpret_cast<const float4*>(x + (size_t)n * CIN * HW + s);
    uint32_t w0 = 0, w1 = 0, w2 = 0, w3 = 0;
#pragma unroll
    for (int c0 = 0; c0 < CIN; c0 += 8) {
        float4 v[8];
#pragma unroll
        for (int j = 0; j < 8; ++j) v[j] = xp[(c0 + j) * (HW / 4)];
#pragma unroll
        for (int j = 0; j < 8; ++j) {
            uint32_t b = 1u << (c0 + j);
            if (v[j].x >= 0.0f) w0 |= b;
            if (v[j].y >= 0.0f) w1 |= b;
            if (v[j].z >= 0.0f) w2 |= b;
            if (v[j].w >= 0.0f) w3 |= b;
        }
    }
    *reinterpret_cast<uint4*>(&g_xpack[p0]) = make_uint4(w0, w1, w2, w3);
}

__device__ __forceinline__ void csa(uint32_t a, uint32_t b, uint32_t c,
                                    uint32_t& s, uint32_t& cy) {
    s  = a ^ b ^ c;                     // LOP3 0x96
    cy = (a & b) | (c & (a | b));       // LOP3 0xE8 (majority)
}

__device__ __forceinline__ void ldrow(uint32_t* a, const uint32_t* p) {
    uint4 v4 = *reinterpret_cast<const uint4*>(p);
    uint2 v2 = *reinterpret_cast<const uint2*>(p + 4);
    a[0] = v4.x; a[1] = v4.y; a[2] = v4.z; a[3] = v4.w; a[4] = v2.x; a[5] = v2.y;
}

// ============================================================================
// Conv: block = (n, cout-group of 8, 16 rows x 128 cols). Warp owns one cout.
// Template B: 0 = interior rows (no h-border code at all), 1 = top, 2 = bottom.
// Tile rows rolled through a [3][6] register file (mod-3 + full unroll -> no
// MOVs, 2 LDS per row-iter instead of 6).
// Inner loop per pixel: 9 XOR + 10 LOP3 + 4 POPC (quarter-rate), I2F-free
// epilogue via 0x4B000000 bit hack (u in [32,992] -> exact).
// ============================================================================
template<int B>
__global__ __launch_bounds__(256) void conv_kernel(
        float* __restrict__ out,
        const float* __restrict__ wgt,
        const float* __restrict__ gamma, const float* __restrict__ beta,
        const float* __restrict__ mean,  const float* __restrict__ var) {
    __shared__ uint32_t tile[18][132];       // 16+2 halo rows, 130 used cols

    int tid     = threadIdx.x;
    int n       = blockIdx.z >> 2;
    int cg      = blockIdx.z & 3;
    int rowbase = (B == 0) ? (int)(blockIdx.y + 1) * 16 : (B == 1 ? 0 : HH - 16);
    int colbase = blockIdx.x * 128;

    const uint32_t* xp = g_xpack + n * HW;
    for (int i = tid; i < 18 * 130; i += 256) {
        int r = i / 130, c = i % 130;
        int h = rowbase - 1 + r;
        int w = colbase - 1 + c;
        uint32_t v = 0;
        if ((unsigned)h < HH && (unsigned)w < WW) v = xp[h * WW + w];
        tile[r][c] = v;
    }

    int wid = tid >> 5, tx = tid & 31;
    int co  = cg * 8 + wid;

    // pack this warp's cout weights via ballot: lane = input channel
    // wb = sign(sign(w)+0.01) -> bit = (w >= 0)
    const float* wp = wgt + (size_t)co * CIN * 9 + tx * 9;
    uint32_t wv0 = __ballot_sync(0xFFFFFFFFu, wp[0] >= 0.0f);
    uint32_t wv1 = __ballot_sync(0xFFFFFFFFu, wp[1] >= 0.0f);
    uint32_t wv2 = __ballot_sync(0xFFFFFFFFu, wp[2] >= 0.0f);
    uint32_t wv3 = __ballot_sync(0xFFFFFFFFu, wp[3] >= 0.0f);
    uint32_t wv4 = __ballot_sync(0xFFFFFFFFu, wp[4] >= 0.0f);
    uint32_t wv5 = __ballot_sync(0xFFFFFFFFu, wp[5] >= 0.0f);
    uint32_t wv6 = __ballot_sync(0xFFFFFFFFu, wp[6] >= 0.0f);
    uint32_t wv7 = __ballot_sync(0xFFFFFFFFu, wp[7] >= 0.0f);
    uint32_t wv8 = __ballot_sync(0xFFFFFFFFu, wp[8] >= 0.0f);

    float sc = gamma[co] * rsqrtf(var[co] + EPSV);
    float bb = (beta[co] - mean[co] * sc) - 512.0f * sc;   // out = fma(sc, u, bb)

    int pw0 = 16 - __popc(wv0), pw2 = 16 - __popc(wv2);
    int pw3 = 16 - __popc(wv3), pw5 = 16 - __popc(wv5);
    int pw6 = 16 - __popc(wv6), pw8 = 16 - __popc(wv8);
    int adjL = pw0 + pw3 + pw6;
    int adjR = pw2 + pw5 + pw8;

    int  w0c = colbase + tx * 4;
    bool isL = (w0c == 0);
    bool isR = (w0c + 3 == WW - 1);
    int baseL = isL ? adjL : 0;
    int baseR = isR ? adjR : 0;

    // h-border constants only exist in border instantiations
    int adjT = 0, adjB = 0, dt0 = 0, dt3 = 0, db0 = 0, db3 = 0;
    if (B == 1) {
        int pw1 = 16 - __popc(wv1);
        adjT = pw0 + pw1 + pw2;
        dt0 = adjT - (isL ? pw0 : 0); dt3 = adjT - (isR ? pw2 : 0);
    }
    if (B == 2) {
        int pw7 = 16 - __popc(wv7);
        adjB = pw6 + pw7 + pw8;
        db0 = adjB - (isL ? pw6 : 0); db3 = adjB - (isR ? pw8 : 0);
    }

    __syncthreads();

    float* op = out + ((size_t)(n * COUT + co)) * HW + rowbase * WW + w0c;
    int tx4 = tx * 4;

    uint32_t A[3][6];
    ldrow(A[0], &tile[0][tx4]);
    ldrow(A[1], &tile[1][tx4]);

#pragma unroll
    for (int r = 0; r < 16; ++r) {
        ldrow(A[(r + 2) % 3], &tile[r + 2][tx4]);
        const uint32_t* a0 = A[r % 3];
        const uint32_t* a1 = A[(r + 1) % 3];
        const uint32_t* a2 = A[(r + 2) % 3];

        int d[4];
#pragma unroll
        for (int p = 0; p < 4; ++p) {
            uint32_t s1, c1, s2, c2, s3, c3, s4, c4, s5, c5;
            csa(a0[p] ^ wv0, a0[p + 1] ^ wv1, a0[p + 2] ^ wv2, s1, c1);
            csa(a1[p] ^ wv3, a1[p + 1] ^ wv4, a1[p + 2] ^ wv5, s2, c2);
            csa(a2[p] ^ wv6, a2[p + 1] ^ wv7, a2[p + 2] ^ wv8, s3, c3);
            csa(s1, s2, s3, s4, c4);
            csa(c1, c2, c3, s5, c5);
            int t = __popc(c4) + __popc(s5);
            d[p] = __popc(s4) + 2 * t + 4 * __popc(c5);
        }
        d[0] += baseL;
        d[3] += baseR;
        if (B == 1 && r == 0)  { d[0] += dt0; d[1] += adjT; d[2] += adjT; d[3] += dt3; }
        if (B == 2 && r == 15) { d[0] += db0; d[1] += adjB; d[2] += adjB; d[3] += db3; }

        float4 res;
        float* rp = &res.x;
#pragma unroll
        for (int p = 0; p < 4; ++p) {
            int u = 800 - 2 * d[p];                       // in [32, 992] -> exact
            float fu = __int_as_float(0x4B000000u | (uint32_t)u) - 8388608.0f;
            rp[p] = fmaxf(fmaf(sc, fu, bb), 0.0f);
        }
        *reinterpret_cast<float4*>(op + r * WW) = res;
    }
}

extern "C" void kernel_launch(void* const* d_in, const int* in_sizes, int n_in,
                              void* d_out, int out_size) {
    const float* x     = (const float*)d_in[0];
    const float* wgt   = (const float*)d_in[1];
    const float* gamma = (const float*)d_in[2];
    const float* beta  = (const float*)d_in[3];
    const float* mean  = (const float*)d_in[4];
    const float* var   = (const float*)d_in[5];
    float* out = (float*)d_out;

    pack_x_kernel<<<2048, 128>>>(x);                 // 4 pixels/thread

    dim3 gridI(2, 14, 64);                           // interior rows 16..239
    dim3 gridE(2, 1, 64);                            // top / bottom 16-row bands
    conv_kernel<0><<<gridI, 256>>>(out, wgt, gamma, beta, mean, var);
    conv_kernel<1><<<gridE, 256>>>(out, wgt, gamma, beta, mean, var);
    conv_kernel<2><<<gridE, 256>>>(out, wgt, gamma, beta, mean, var);
}

// round 8
// speedup vs baseline: 1.0752x; 1.0752x over previous
#include <cuda_runtime.h>
#include <cstdint>

#define N_IMG 16
#define CIN   32
#define COUT  32
#define HH    256
#define WW    256
#define HW    (HH * WW)
#define EPSV  1e-5f

// ---- scratch (no allocations allowed -> __device__ globals) ----
__device__ uint32_t g_xpack[N_IMG * HW];   // packed sign bits, bit c = (x[c] >= 0)

// ============================================================================
// Pack x: NCHW f32 -> per-pixel 32-bit sign word. Thread = 4 pixels.
// Channels staged in batches of 8 float4 -> MLP ~8. Block=128 for smoother
// SM residency (2048 blocks).
// ============================================================================
__global__ __launch_bounds__(128) void pack_x_kernel(const float* __restrict__ x) {
    int g  = blockIdx.x * 128 + threadIdx.x;
    int p0 = g << 2;
    int n  = p0 >> 16;                     // HW = 65536
    int s  = p0 & (HW - 1);
    const float4* xp = reinterpret_cast<const float4*>(x + (size_t)n * CIN * HW + s);
    uint32_t w0 = 0, w1 = 0, w2 = 0, w3 = 0;
#pragma unroll
    for (int c0 = 0; c0 < CIN; c0 += 8) {
        float4 v[8];
#pragma unroll
        for (int j = 0; j < 8; ++j) v[j] = xp[(c0 + j) * (HW / 4)];
#pragma unroll
        for (int j = 0; j < 8; ++j) {
            uint32_t b = 1u << (c0 + j);
            if (v[j].x >= 0.0f) w0 |= b;
            if (v[j].y >= 0.0f) w1 |= b;
            if (v[j].z >= 0.0f) w2 |= b;
            if (v[j].w >= 0.0f) w3 |= b;
        }
    }
    *reinterpret_cast<uint4*>(&g_xpack[p0]) = make_uint4(w0, w1, w2, w3);
}

__device__ __forceinline__ void csa(uint32_t a, uint32_t b, uint32_t c,
                                    uint32_t& s, uint32_t& cy) {
    s  = a ^ b ^ c;                     // LOP3 0x96
    cy = (a & b) | (c & (a | b));       // LOP3 0xE8 (majority)
}

__device__ __forceinline__ void ldrow(uint32_t* a, const uint32_t* p) {
    uint4 v4 = *reinterpret_cast<const uint4*>(p);
    uint2 v2 = *reinterpret_cast<const uint2*>(p + 4);
    a[0] = v4.x; a[1] = v4.y; a[2] = v4.z; a[3] = v4.w; a[4] = v2.x; a[5] = v2.y;
}

// ============================================================================
// Conv: block = (n, cout-group of 8, 16 rows x 128 cols). Warp owns one cout.
// Template B: 0 = interior rows (no h-border code at all), 1 = edge bands
// (blockIdx.y selects top or bottom).
// Tile rows rolled through a [3][6] register file (mod-3 + full unroll -> no
// MOVs, 2 LDS per row-iter instead of 6).
// Inner loop per pixel: 9 XOR + 10 LOP3 + 4 POPC (quarter-rate), I2F-free
// epilogue via 0x4B000000 bit hack (u in [32,992] -> exact).
// ============================================================================
template<int B>
__global__ __launch_bounds__(256) void conv_kernel(
        float* __restrict__ out,
        const float* __restrict__ wgt,
        const float* __restrict__ gamma, const float* __restrict__ beta,
        const float* __restrict__ mean,  const float* __restrict__ var) {
    __shared__ uint32_t tile[18][132];       // 16+2 halo rows, 130 used cols

    int tid     = threadIdx.x;
    int n       = blockIdx.z >> 2;
    int cg      = blockIdx.z & 3;
    bool isTop  = (B == 1) && (blockIdx.y == 0);
    bool isBot  = (B == 1) && (blockIdx.y == 1);
    int rowbase = (B == 0) ? (int)(blockIdx.y + 1) * 16 : (isTop ? 0 : HH - 16);
    int colbase = blockIdx.x * 128;

    const uint32_t* xp = g_xpack + n * HW;
    for (int i = tid; i < 18 * 130; i += 256) {
        int r = i / 130, c = i % 130;
        int h = rowbase - 1 + r;
        int w = colbase - 1 + c;
        uint32_t v = 0;
        if ((unsigned)h < HH && (unsigned)w < WW) v = xp[h * WW + w];
        tile[r][c] = v;
    }

    int wid = tid >> 5, tx = tid & 31;
    int co  = cg * 8 + wid;

    // pack this warp's cout weights via ballot: lane = input channel
    // wb = sign(sign(w)+0.01) -> bit = (w >= 0)
    const float* wp = wgt + (size_t)co * CIN * 9 + tx * 9;
    uint32_t wv0 = __ballot_sync(0xFFFFFFFFu, wp[0] >= 0.0f);
    uint32_t wv1 = __ballot_sync(0xFFFFFFFFu, wp[1] >= 0.0f);
    uint32_t wv2 = __ballot_sync(0xFFFFFFFFu, wp[2] >= 0.0f);
    uint32_t wv3 = __ballot_sync(0xFFFFFFFFu, wp[3] >= 0.0f);
    uint32_t wv4 = __ballot_sync(0xFFFFFFFFu, wp[4] >= 0.0f);
    uint32_t wv5 = __ballot_sync(0xFFFFFFFFu, wp[5] >= 0.0f);
    uint32_t wv6 = __ballot_sync(0xFFFFFFFFu, wp[6] >= 0.0f);
    uint32_t wv7 = __ballot_sync(0xFFFFFFFFu, wp[7] >= 0.0f);
    uint32_t wv8 = __ballot_sync(0xFFFFFFFFu, wp[8] >= 0.0f);

    float sc = gamma[co] * rsqrtf(var[co] + EPSV);
    float bb = (beta[co] - mean[co] * sc) - 512.0f * sc;   // out = fma(sc, u, bb)

    int pw0 = 16 - __popc(wv0), pw2 = 16 - __popc(wv2);
    int pw3 = 16 - __popc(wv3), pw5 = 16 - __popc(wv5);
    int pw6 = 16 - __popc(wv6), pw8 = 16 - __popc(wv8);
    int adjL = pw0 + pw3 + pw6;
    int adjR = pw2 + pw5 + pw8;

    int  w0c = colbase + tx * 4;
    bool isL = (w0c == 0);
    bool isR = (w0c + 3 == WW - 1);
    int baseL = isL ? adjL : 0;
    int baseR = isR ? adjR : 0;

    // h-border constants only exist in the edge instantiation
    int adjE = 0, de0 = 0, de3 = 0;
    if (B == 1) {
        if (isTop) {
            int pw1 = 16 - __popc(wv1);
            adjE = pw0 + pw1 + pw2;
            de0 = adjE - (isL ? pw0 : 0); de3 = adjE - (isR ? pw2 : 0);
        } else {
            int pw7 = 16 - __popc(wv7);
            adjE = pw6 + pw7 + pw8;
            de0 = adjE - (isL ? pw6 : 0); de3 = adjE - (isR ? pw8 : 0);
        }
    }

    __syncthreads();

    float* op = out + ((size_t)(n * COUT + co)) * HW + rowbase * WW + w0c;
    int tx4 = tx * 4;

    uint32_t A[3][6];
    ldrow(A[0], &tile[0][tx4]);
    ldrow(A[1], &tile[1][tx4]);

#pragma unroll
    for (int r = 0; r < 16; ++r) {
        ldrow(A[(r + 2) % 3], &tile[r + 2][tx4]);
        const uint32_t* a0 = A[r % 3];
        const uint32_t* a1 = A[(r + 1) % 3];
        const uint32_t* a2 = A[(r + 2) % 3];

        int d[4];
#pragma unroll
        for (int p = 0; p < 4; ++p) {
            uint32_t s1, c1, s2, c2, s3, c3, s4, c4, s5, c5;
            csa(a0[p] ^ wv0, a0[p + 1] ^ wv1, a0[p + 2] ^ wv2, s1, c1);
            csa(a1[p] ^ wv3, a1[p + 1] ^ wv4, a1[p + 2] ^ wv5, s2, c2);
            csa(a2[p] ^ wv6, a2[p + 1] ^ wv7, a2[p + 2] ^ wv8, s3, c3);
            csa(s1, s2, s3, s4, c4);
            csa(c1, c2, c3, s5, c5);
            int t = __popc(c4) + __popc(s5);
            d[p] = __popc(s4) + 2 * t + 4 * __popc(c5);
        }
        d[0] += baseL;
        d[3] += baseR;
        if (B == 1) {
            bool edgeRow = (isTop && r == 0) || (isBot && r == 15);
            if (edgeRow) { d[0] += de0; d[1] += adjE; d[2] += adjE; d[3] += de3; }
        }

        float4 res;
        float* rp = &res.x;
#pragma unroll
        for (int p = 0; p < 4; ++p) {
            int u = 800 - 2 * d[p];                       // in [32, 992] -> exact
            float fu = __int_as_float(0x4B000000u | (uint32_t)u) - 8388608.0f;
            rp[p] = fmaxf(fmaf(sc, fu, bb), 0.0f);
        }
        *reinterpret_cast<float4*>(op + r * WW) = res;
    }
}

extern "C" void kernel_launch(void* const* d_in, const int* in_sizes, int n_in,
                              void* d_out, int out_size) {
    const float* x     = (const float*)d_in[0];
    const float* wgt   = (const float*)d_in[1];
    const float* gamma = (const float*)d_in[2];
    const float* beta  = (const float*)d_in[3];
    const float* mean  = (const float*)d_in[4];
    const float* var   = (const float*)d_in[5];
    float* out = (float*)d_out;

    pack_x_kernel<<<2048, 128>>>(x);                 // 4 pixels/thread

    dim3 gridI(2, 14, 64);                           // interior rows 16..239
    dim3 gridE(2, 2, 64);                            // top + bottom 16-row bands
    conv_kernel<0><<<gridI, 256>>>(out, wgt, gamma, beta, mean, var);
    conv_kernel<1><<<gridE, 256>>>(out, wgt, gamma, beta, mean, var);
}